// round 14
// baseline (speedup 1.0000x reference)
#include <cuda_runtime.h>

// Problem dims (fixed by the dataset)
#define BDIM 64
#define NDIM 512
#define HDIM 2048
#define KP     (NDIM / 2)     // 256 packed k-pairs
#define HC     64             // h-chunk per prod block
#define NCHUNK (HDIM / HC)    // 32 partial-product chunks
#define NKPG   (KP / 32)      // 8 kp-groups (blocks per chunk)
#define NSPLIT 8              // n-split for z-GEMM
#define NCK    (NDIM / NSPLIT)

// ---------------------------------------------------------------------------
// Device scratch (allocation-free rule: __device__ globals)
// ---------------------------------------------------------------------------
__device__ float              g_Tt[HDIM * BDIM];                  // [h][b] = tanh(z[b][h])
__device__ unsigned long long g_zp[NSPLIT * HDIM * (BDIM / 2)];   // z partials [ns][h][bp] packed
__device__ unsigned long long g_Ppart[NCHUNK * BDIM * KP];        // [c][b][kp] partial ratio-products
__device__ int                g_cnt[NCHUNK];                      // combine-done counters per chunk

// ---------------------------------------------------------------------------
// f32x2 packed helpers
// ---------------------------------------------------------------------------
__device__ __forceinline__ unsigned long long pk2(float lo, float hi) {
    unsigned long long r;
    asm("mov.b64 %0, {%1, %2};" : "=l"(r) : "f"(lo), "f"(hi));
    return r;
}
__device__ __forceinline__ unsigned long long fma2(unsigned long long a, unsigned long long b, unsigned long long c) {
    unsigned long long r;
    asm("fma.rn.f32x2 %0, %1, %2, %3;" : "=l"(r) : "l"(a), "l"(b), "l"(c));
    return r;
}
__device__ __forceinline__ unsigned long long mul2(unsigned long long a, unsigned long long b) {
    unsigned long long r;
    asm("mul.rn.f32x2 %0, %1, %2;" : "=l"(r) : "l"(a), "l"(b));
    return r;
}
__device__ __forceinline__ unsigned long long add2(unsigned long long a, unsigned long long b) {
    unsigned long long r;
    asm("add.rn.f32x2 %0, %1, %2;" : "=l"(r) : "l"(a), "l"(b));
    return r;
}
__device__ __forceinline__ float2 up2(unsigned long long p) {
    float lo, hi;
    asm("mov.b64 {%0, %1}, %2;" : "=f"(lo), "=f"(hi) : "l"(p));
    return make_float2(lo, hi);
}
__device__ __forceinline__ float tanh_fast(float v) {
    float r;
    asm("tanh.approx.f32 %0, %1;" : "=f"(r) : "f"(v));
    return r;
}
__device__ __forceinline__ int ld_acquire(const int* p) {
    int v;
    asm volatile("ld.acquire.gpu.s32 %0, [%1];" : "=r"(v) : "l"(p) : "memory");
    return v;
}

// ---------------------------------------------------------------------------
// Kernel 1: z partials (R9-proven shape) + zero the chunk counters.
// Thread = (1 h, 16 b as 8 packed accs), n-chunk NCK=64.
// grid (HDIM/256, BDIM/16, NSPLIT) = (8, 4, 8) = 256 blocks, block 256.
// ---------------------------------------------------------------------------
__global__ void __launch_bounds__(256) z_part_kernel(const float* __restrict__ W,
                                                     const float* __restrict__ x) {
    __shared__ float sx[NCK][16];  // [n_local][b_local]
    int t  = threadIdx.x;
    int h  = blockIdx.x * 256 + t;
    int b0 = blockIdx.y * 16;
    int n0 = blockIdx.z * NCK;

    // zero prod's combine counters (prod runs strictly after this kernel)
    if (blockIdx.x == 0 && blockIdx.y == 0 && blockIdx.z == 0 && t < NCHUNK)
        g_cnt[t] = 0;

#pragma unroll
    for (int j = 0; j < 4; j++) {
        int idx = t + j * 256;               // 0..1023
        int bl = idx >> 6, nl = idx & 63;
        sx[nl][bl] = __ldg(x + (size_t)(b0 + bl) * NDIM + n0 + nl);
    }
    __syncthreads();

    unsigned long long acc[8];
#pragma unroll
    for (int i = 0; i < 8; i++) acc[i] = 0;  // packed +0.0

    const float* wp = W + (size_t)n0 * HDIM + h;
#pragma unroll 4
    for (int n = 0; n < NCK; n++) {
        float w = __ldg(wp + n * HDIM);      // coalesced across threads
        unsigned long long wd = pk2(w, w);
        const ulonglong2* xr = reinterpret_cast<const ulonglong2*>(&sx[n][0]);
        ulonglong2 xA = xr[0];               // b0+0..3  (broadcast)
        ulonglong2 xB = xr[1];               // b0+4..7
        ulonglong2 xC = xr[2];               // b0+8..11
        ulonglong2 xD = xr[3];               // b0+12..15
        acc[0] = fma2(xA.x, wd, acc[0]);
        acc[1] = fma2(xA.y, wd, acc[1]);
        acc[2] = fma2(xB.x, wd, acc[2]);
        acc[3] = fma2(xB.y, wd, acc[3]);
        acc[4] = fma2(xC.x, wd, acc[4]);
        acc[5] = fma2(xC.y, wd, acc[5]);
        acc[6] = fma2(xD.x, wd, acc[6]);
        acc[7] = fma2(xD.y, wd, acc[7]);
    }
    int bp0 = blockIdx.y * 8;
    ulonglong2* zp = reinterpret_cast<ulonglong2*>(
        g_zp + ((size_t)blockIdx.z * HDIM + h) * (BDIM / 2) + bp0);
#pragma unroll
    for (int i = 0; i < 4; i++)
        zp[i] = make_ulonglong2(acc[2 * i], acc[2 * i + 1]);
}

// ---------------------------------------------------------------------------
// Kernel 2: prod with fused z-combine (no duplication, flag-synced) + C/S gen.
//   Ppart[c][b][k] = prod_{h in chunk} ( cosh(2W[k,h]) - x[b,k]*tanh(z[b,h])*sinh(2W[k,h]) )
// grid (NKPG, 1, NCHUNK) = 256 blocks (single co-resident wave), block 256.
// Phase A: block (kpg,c) combines its 1/8 slice of chunk c's (h,b) cells
//          (1 cell/thread, 8 MLP loads + tree add + bias + tanh.approx),
//          writes Tt, fence, atomicAdd(cnt[c]).
// Phase B: build C/S smem tile from W (overlaps other blocks' combine skew).
// Phase C: poll cnt[c]==NKPG (acquire), then the R9 main product loop.
// ---------------------------------------------------------------------------
__global__ void __launch_bounds__(256, 2) prod_kernel(const float* __restrict__ W,
                                                      const float* __restrict__ x,
                                                      const float* __restrict__ bias) {
    __shared__ float sC[HC][66];   // pad 66: conflict-free, LDS.64-aligned
    __shared__ float sS[HC][66];
    int t    = threadIdx.x;
    int lane = t & 31;
    int w    = t >> 5;
    int kpg  = blockIdx.x;
    int c    = blockIdx.z;
    int k0   = kpg * 64;           // 64 k = 32 kp per block
    int h0   = c * HC;

    // --- Phase A: combine z partials for this block's slice of chunk c ---
    {
        int cell = kpg * 256 + t;            // 0..2047 over (64h x 32bp)
        int hl = cell >> 5, bp = cell & 31;  // hl in [kpg*8, kpg*8+8)
        const unsigned long long* zp = g_zp + (size_t)(h0 + hl) * (BDIM / 2) + bp;
        unsigned long long v[NSPLIT];
#pragma unroll
        for (int ns = 0; ns < NSPLIT; ns++)
            v[ns] = __ldg(zp + (size_t)ns * (HDIM * BDIM / 2));
        unsigned long long s = add2(add2(add2(v[0], v[1]), add2(v[2], v[3])),
                                    add2(add2(v[4], v[5]), add2(v[6], v[7])));
        float2 z = up2(s);
        float bv = __ldg(bias + h0 + hl);
        *reinterpret_cast<float2*>(g_Tt + (size_t)(h0 + hl) * BDIM + 2 * bp) =
            make_float2(tanh_fast(z.x + bv), tanh_fast(z.y + bv));
    }
    __threadfence();               // release Tt writes
    __syncthreads();
    if (t == 0) atomicAdd(&g_cnt[c], 1);

    // --- Phase B: C/S build (independent of Tt) ---
#pragma unroll
    for (int j = 0; j < 16; j++) {
        int idx = t + j * 256;                // 0..4095 over 64k x 64h
        int hl = idx & 63, kl = idx >> 6;
        float wv = __ldg(W + (size_t)(k0 + kl) * HDIM + h0 + hl);
        float e  = __expf(2.0f * wv);
        float ei = __expf(-2.0f * wv);
        sC[hl][kl] = 0.5f * (e + ei);
        sS[hl][kl] = 0.5f * (e - ei);
    }

    // -x signs for 8 b at this thread's kp (LDG.64, XOR sign flip)
    int b0 = w * 8;
    unsigned long long nx[8];
#pragma unroll
    for (int i = 0; i < 8; i++) {
        unsigned long long xv = *reinterpret_cast<const unsigned long long*>(
            x + (size_t)(b0 + i) * NDIM + k0 + 2 * lane);
        nx[i] = xv ^ 0x8000000080000000ULL;
    }
    __syncthreads();               // smem tile ready

    // --- Phase C: wait for all 8 kpg blocks of this chunk, then main loop ---
    if (t == 0) {
        while (ld_acquire(&g_cnt[c]) < NKPG) __nanosleep(32);
    }
    __syncthreads();

    const float4* tp = reinterpret_cast<const float4*>(g_Tt + (size_t)h0 * BDIM + b0);

    unsigned long long acc[8];
#pragma unroll
    for (int i = 0; i < 8; i++) acc[i] = pk2(1.0f, 1.0f);

#pragma unroll 4
    for (int h = 0; h < HC; h++) {
        unsigned long long Cp = *reinterpret_cast<const unsigned long long*>(&sC[h][2 * lane]);
        unsigned long long Sp = *reinterpret_cast<const unsigned long long*>(&sS[h][2 * lane]);
        float4 ta = tp[h * (BDIM / 4)];       // tanh b0..b0+3 (uniform; plain load — coherent)
        float4 tb = tp[h * (BDIM / 4) + 1];   // tanh b0+4..b0+7
        acc[0] = mul2(acc[0], fma2(mul2(nx[0], pk2(ta.x, ta.x)), Sp, Cp));
        acc[1] = mul2(acc[1], fma2(mul2(nx[1], pk2(ta.y, ta.y)), Sp, Cp));
        acc[2] = mul2(acc[2], fma2(mul2(nx[2], pk2(ta.z, ta.z)), Sp, Cp));
        acc[3] = mul2(acc[3], fma2(mul2(nx[3], pk2(ta.w, ta.w)), Sp, Cp));
        acc[4] = mul2(acc[4], fma2(mul2(nx[4], pk2(tb.x, tb.x)), Sp, Cp));
        acc[5] = mul2(acc[5], fma2(mul2(nx[5], pk2(tb.y, tb.y)), Sp, Cp));
        acc[6] = mul2(acc[6], fma2(mul2(nx[6], pk2(tb.z, tb.z)), Sp, Cp));
        acc[7] = mul2(acc[7], fma2(mul2(nx[7], pk2(tb.w, tb.w)), Sp, Cp));
    }

    int kp = kpg * 32 + lane;
    unsigned long long* out = g_Ppart + (size_t)c * (BDIM * KP);
#pragma unroll
    for (int i = 0; i < 8; i++)
        out[(size_t)(b0 + i) * KP + kp] = acc[i];
}

// ---------------------------------------------------------------------------
// Kernel 3: fused reduce, chunk-product parallelized across threads.
// grid BDIM, block 1024: thread = (kp, cg), cg in 0..3, each multiplies 8
// independent chunk values (MLP-8); partials combined via smem; first 256
// threads apply ea = Oxy*exp(-2*x*a) and tree-sum over k.
// ---------------------------------------------------------------------------
__global__ void __launch_bounds__(1024) reduce_kernel(const float* __restrict__ x,
                                                      const float* __restrict__ a,
                                                      const float* __restrict__ Oxy,
                                                      float* __restrict__ out) {
    __shared__ unsigned long long sp[1024];
    __shared__ float ssum[8];
    int b  = blockIdx.x;
    int t  = threadIdx.x;
    int kp = t & 255;
    int cg = t >> 8;            // 0..3 -> chunks cg*8 .. cg*8+7

    const unsigned long long* P =
        g_Ppart + (size_t)(cg * 8) * (BDIM * KP) + (size_t)b * KP + kp;
    unsigned long long v[8];
#pragma unroll
    for (int i = 0; i < 8; i++)
        v[i] = __ldg(P + (size_t)i * (BDIM * KP));
    sp[t] = mul2(mul2(mul2(v[0], v[1]), mul2(v[2], v[3])),
                 mul2(mul2(v[4], v[5]), mul2(v[6], v[7])));
    __syncthreads();

    if (t < 256) {
        unsigned long long p = mul2(mul2(sp[t], sp[t + 256]),
                                    mul2(sp[t + 512], sp[t + 768]));
        float2 pf = up2(p);
        float2 xv = *reinterpret_cast<const float2*>(x + (size_t)b * NDIM + 2 * kp);
        float2 av = *reinterpret_cast<const float2*>(a + 2 * kp);
        float2 ov = *reinterpret_cast<const float2*>(Oxy + 2 * kp);
        float e0 = ov.x * __expf(-2.0f * xv.x * av.x);
        float e1 = ov.y * __expf(-2.0f * xv.y * av.y);
        float s = pf.x * e0 + pf.y * e1;

#pragma unroll
        for (int o = 16; o; o >>= 1) s += __shfl_xor_sync(0xffffffffu, s, o);
        if ((t & 31) == 0) ssum[t >> 5] = s;
    }
    __syncthreads();
    if (t < 8) {
        float s2 = ssum[t];
#pragma unroll
        for (int o = 4; o; o >>= 1) s2 += __shfl_xor_sync(0x000000ffu, s2, o);
        if (t == 0) out[b] = s2;
    }
}

// ---------------------------------------------------------------------------
// Launch: 3 kernels
// ---------------------------------------------------------------------------
extern "C" void kernel_launch(void* const* d_in, const int* in_sizes, int n_in,
                              void* d_out, int out_size) {
    const float* x    = (const float*)d_in[0];   // [64,512]
    const float* W    = (const float*)d_in[1];   // [512,2048]
    const float* bias = (const float*)d_in[2];   // [2048]
    const float* a    = (const float*)d_in[3];   // [512]
    const float* Oxy  = (const float*)d_in[4];   // [512]
    float* out = (float*)d_out;                  // [64]

    z_part_kernel<<<dim3(HDIM / 256, BDIM / 16, NSPLIT), 256>>>(W, x);
    prod_kernel<<<dim3(NKPG, 1, NCHUNK), 256>>>(W, x, bias);
    reduce_kernel<<<BDIM, 1024>>>(x, a, Oxy, out);
}

// round 15
// speedup vs baseline: 1.4595x; 1.4595x over previous
#include <cuda_runtime.h>

// Problem dims (fixed by the dataset)
#define BDIM 64
#define NDIM 512
#define HDIM 2048
#define KP     (NDIM / 2)     // 256 packed k-pairs
#define HC     64             // h-chunk per prod block
#define NCHUNK (HDIM / HC)    // 32 partial-product chunks
#define NSPLIT 8              // n-split for z-GEMM
#define NCK    (NDIM / NSPLIT)

// ---------------------------------------------------------------------------
// Device scratch (allocation-free rule: __device__ globals)
// ---------------------------------------------------------------------------
__device__ float              g_Tt[HDIM * BDIM];                  // [h][b] = tanh(z[b][h])
__device__ unsigned long long g_zp[NSPLIT * HDIM * (BDIM / 2)];   // z partials [ns][h][bp] packed
__device__ unsigned long long g_Ppart[NCHUNK * BDIM * KP];        // [c][b][kp] partial ratio-products

// ---------------------------------------------------------------------------
// f32x2 packed helpers
// ---------------------------------------------------------------------------
__device__ __forceinline__ unsigned long long pk2(float lo, float hi) {
    unsigned long long r;
    asm("mov.b64 %0, {%1, %2};" : "=l"(r) : "f"(lo), "f"(hi));
    return r;
}
__device__ __forceinline__ unsigned long long fma2(unsigned long long a, unsigned long long b, unsigned long long c) {
    unsigned long long r;
    asm("fma.rn.f32x2 %0, %1, %2, %3;" : "=l"(r) : "l"(a), "l"(b), "l"(c));
    return r;
}
__device__ __forceinline__ unsigned long long mul2(unsigned long long a, unsigned long long b) {
    unsigned long long r;
    asm("mul.rn.f32x2 %0, %1, %2;" : "=l"(r) : "l"(a), "l"(b));
    return r;
}
__device__ __forceinline__ unsigned long long add2(unsigned long long a, unsigned long long b) {
    unsigned long long r;
    asm("add.rn.f32x2 %0, %1, %2;" : "=l"(r) : "l"(a), "l"(b));
    return r;
}
__device__ __forceinline__ float2 up2(unsigned long long p) {
    float lo, hi;
    asm("mov.b64 {%0, %1}, %2;" : "=f"(lo), "=f"(hi) : "l"(p));
    return make_float2(lo, hi);
}
__device__ __forceinline__ float tanh_fast(float v) {
    float r;
    asm("tanh.approx.f32 %0, %1;" : "=f"(r) : "f"(v));
    return r;
}

// ---------------------------------------------------------------------------
// Kernel 1: z partials. Thread = (1 h, 16 b as 8 packed accs), n-chunk NCK=64.
// grid (HDIM/256, BDIM/16, NSPLIT) = (8, 4, 8) = 256 blocks, block 256.
// ---------------------------------------------------------------------------
__global__ void __launch_bounds__(256) z_part_kernel(const float* __restrict__ W,
                                                     const float* __restrict__ x) {
    __shared__ float sx[NCK][16];  // [n_local][b_local]
    int t  = threadIdx.x;
    int h  = blockIdx.x * 256 + t;
    int b0 = blockIdx.y * 16;
    int n0 = blockIdx.z * NCK;

#pragma unroll
    for (int j = 0; j < 4; j++) {
        int idx = t + j * 256;               // 0..1023
        int bl = idx >> 6, nl = idx & 63;
        sx[nl][bl] = __ldg(x + (size_t)(b0 + bl) * NDIM + n0 + nl);
    }
    __syncthreads();

    unsigned long long acc[8];
#pragma unroll
    for (int i = 0; i < 8; i++) acc[i] = 0;  // packed +0.0

    const float* wp = W + (size_t)n0 * HDIM + h;
#pragma unroll 4
    for (int n = 0; n < NCK; n++) {
        float w = __ldg(wp + n * HDIM);      // coalesced across threads
        unsigned long long wd = pk2(w, w);
        const ulonglong2* xr = reinterpret_cast<const ulonglong2*>(&sx[n][0]);
        ulonglong2 xA = xr[0];               // b0+0..3  (broadcast)
        ulonglong2 xB = xr[1];               // b0+4..7
        ulonglong2 xC = xr[2];               // b0+8..11
        ulonglong2 xD = xr[3];               // b0+12..15
        acc[0] = fma2(xA.x, wd, acc[0]);
        acc[1] = fma2(xA.y, wd, acc[1]);
        acc[2] = fma2(xB.x, wd, acc[2]);
        acc[3] = fma2(xB.y, wd, acc[3]);
        acc[4] = fma2(xC.x, wd, acc[4]);
        acc[5] = fma2(xC.y, wd, acc[5]);
        acc[6] = fma2(xD.x, wd, acc[6]);
        acc[7] = fma2(xD.y, wd, acc[7]);
    }
    int bp0 = blockIdx.y * 8;
    ulonglong2* zp = reinterpret_cast<ulonglong2*>(
        g_zp + ((size_t)blockIdx.z * HDIM + h) * (BDIM / 2) + bp0);
#pragma unroll
    for (int i = 0; i < 4; i++)
        zp[i] = make_ulonglong2(acc[2 * i], acc[2 * i + 1]);
}

// ---------------------------------------------------------------------------
// Kernel 2: combine z partials + bias, tanh.approx, write Tt[h][b].
// grid 256, block 256 (thread = (h, bp)); 8 independent loads (MLP 8).
// ---------------------------------------------------------------------------
__global__ void __launch_bounds__(256) z_comb_kernel(const float* __restrict__ bias) {
    int idx = blockIdx.x * 256 + threadIdx.x;   // 0..65535
    int h = idx >> 5, bp = idx & 31;
    const unsigned long long* zp = g_zp + (size_t)h * (BDIM / 2) + bp;
    unsigned long long v[NSPLIT];
#pragma unroll
    for (int ns = 0; ns < NSPLIT; ns++)
        v[ns] = __ldg(zp + (size_t)ns * (HDIM * BDIM / 2));
    unsigned long long s = add2(add2(add2(v[0], v[1]), add2(v[2], v[3])),
                                add2(add2(v[4], v[5]), add2(v[6], v[7])));
    float2 z = up2(s);
    float bv = bias[h];
    float2 tv = make_float2(tanh_fast(z.x + bv), tanh_fast(z.y + bv));
    *reinterpret_cast<float2*>(g_Tt + (size_t)h * BDIM + 2 * bp) = tv;
}

// ---------------------------------------------------------------------------
// Kernel 3: main product kernel with fused C/S generation.
//   Ppart[c][b][k] = prod_{h in chunk} ( cosh(2W[k,h]) - x[b,k]*tanh(z[b,h])*sinh(2W[k,h]) )
// Thread tile: 1 kp (2 k) x 8 b over 64 h. grid (KP/32, 1, NCHUNK) = 256
// blocks, block 256, 2 blocks/SM -> single wave on 148 SMs.
// ---------------------------------------------------------------------------
__global__ void __launch_bounds__(256, 2) prod_kernel(const float* __restrict__ W,
                                                      const float* __restrict__ x) {
    __shared__ float sC[HC][66];   // pad 66: conflict-free, LDS.64-aligned
    __shared__ float sS[HC][66];
    int t    = threadIdx.x;
    int lane = t & 31;
    int w    = t >> 5;
    int k0   = blockIdx.x * 64;    // 64 k = 32 kp per block
    int h0   = blockIdx.z * HC;

    // Build C/S tile: coalesced W reads (lanes cover consecutive h), MUFU expf
#pragma unroll
    for (int j = 0; j < 16; j++) {
        int idx = t + j * 256;                // 0..4095 over 64k x 64h
        int hl = idx & 63, kl = idx >> 6;
        float wv = __ldg(W + (size_t)(k0 + kl) * HDIM + h0 + hl);
        float e  = __expf(2.0f * wv);
        float ei = __expf(-2.0f * wv);
        sC[hl][kl] = 0.5f * (e + ei);
        sS[hl][kl] = 0.5f * (e - ei);
    }

    // -x signs for 8 b at this thread's kp (LDG.64, XOR sign flip)
    int b0 = w * 8;
    unsigned long long nx[8];
#pragma unroll
    for (int i = 0; i < 8; i++) {
        unsigned long long xv = *reinterpret_cast<const unsigned long long*>(
            x + (size_t)(b0 + i) * NDIM + k0 + 2 * lane);
        nx[i] = xv ^ 0x8000000080000000ULL;
    }
    __syncthreads();

    const float4* tp = reinterpret_cast<const float4*>(g_Tt + (size_t)h0 * BDIM + b0);

    unsigned long long acc[8];
#pragma unroll
    for (int i = 0; i < 8; i++) acc[i] = pk2(1.0f, 1.0f);

#pragma unroll 4
    for (int h = 0; h < HC; h++) {
        unsigned long long Cp = *reinterpret_cast<const unsigned long long*>(&sC[h][2 * lane]);
        unsigned long long Sp = *reinterpret_cast<const unsigned long long*>(&sS[h][2 * lane]);
        float4 ta = __ldg(tp + h * (BDIM / 4));       // tanh b0..b0+3 (uniform)
        float4 tb = __ldg(tp + h * (BDIM / 4) + 1);   // tanh b0+4..b0+7
        acc[0] = mul2(acc[0], fma2(mul2(nx[0], pk2(ta.x, ta.x)), Sp, Cp));
        acc[1] = mul2(acc[1], fma2(mul2(nx[1], pk2(ta.y, ta.y)), Sp, Cp));
        acc[2] = mul2(acc[2], fma2(mul2(nx[2], pk2(ta.z, ta.z)), Sp, Cp));
        acc[3] = mul2(acc[3], fma2(mul2(nx[3], pk2(ta.w, ta.w)), Sp, Cp));
        acc[4] = mul2(acc[4], fma2(mul2(nx[4], pk2(tb.x, tb.x)), Sp, Cp));
        acc[5] = mul2(acc[5], fma2(mul2(nx[5], pk2(tb.y, tb.y)), Sp, Cp));
        acc[6] = mul2(acc[6], fma2(mul2(nx[6], pk2(tb.z, tb.z)), Sp, Cp));
        acc[7] = mul2(acc[7], fma2(mul2(nx[7], pk2(tb.w, tb.w)), Sp, Cp));
    }

    int kp = blockIdx.x * 32 + lane;
    unsigned long long* out = g_Ppart + (size_t)blockIdx.z * (BDIM * KP);
#pragma unroll
    for (int i = 0; i < 8; i++)
        out[(size_t)(b0 + i) * KP + kp] = acc[i];
}

// ---------------------------------------------------------------------------
// Kernel 4: fused reduce, chunk-product parallelized across threads.
// grid BDIM, block 1024: thread = (kp, cg), cg in 0..3, each multiplies 8
// independent chunk values (MLP-8); partials combined via smem; first 256
// threads apply ea = Oxy*exp(-2*x*a) and tree-sum over k.
// ---------------------------------------------------------------------------
__global__ void __launch_bounds__(1024) reduce_kernel(const float* __restrict__ x,
                                                      const float* __restrict__ a,
                                                      const float* __restrict__ Oxy,
                                                      float* __restrict__ out) {
    __shared__ unsigned long long sp[1024];
    __shared__ float ssum[8];
    int b  = blockIdx.x;
    int t  = threadIdx.x;
    int kp = t & 255;
    int cg = t >> 8;            // 0..3 -> chunks cg*8 .. cg*8+7

    const unsigned long long* P =
        g_Ppart + (size_t)(cg * 8) * (BDIM * KP) + (size_t)b * KP + kp;
    unsigned long long v[8];
#pragma unroll
    for (int i = 0; i < 8; i++)
        v[i] = __ldg(P + (size_t)i * (BDIM * KP));
    sp[t] = mul2(mul2(mul2(v[0], v[1]), mul2(v[2], v[3])),
                 mul2(mul2(v[4], v[5]), mul2(v[6], v[7])));
    __syncthreads();

    if (t < 256) {
        unsigned long long p = mul2(mul2(sp[t], sp[t + 256]),
                                    mul2(sp[t + 512], sp[t + 768]));
        float2 pf = up2(p);
        float2 xv = *reinterpret_cast<const float2*>(x + (size_t)b * NDIM + 2 * kp);
        float2 av = *reinterpret_cast<const float2*>(a + 2 * kp);
        float2 ov = *reinterpret_cast<const float2*>(Oxy + 2 * kp);
        float e0 = ov.x * __expf(-2.0f * xv.x * av.x);
        float e1 = ov.y * __expf(-2.0f * xv.y * av.y);
        float s = pf.x * e0 + pf.y * e1;

#pragma unroll
        for (int o = 16; o; o >>= 1) s += __shfl_xor_sync(0xffffffffu, s, o);
        if ((t & 31) == 0) ssum[t >> 5] = s;
    }
    __syncthreads();
    if (t < 8) {
        float s2 = ssum[t];
#pragma unroll
        for (int o = 4; o; o >>= 1) s2 += __shfl_xor_sync(0x000000ffu, s2, o);
        if (t == 0) out[b] = s2;
    }
}

// ---------------------------------------------------------------------------
// Launch: 4 kernels
// ---------------------------------------------------------------------------
extern "C" void kernel_launch(void* const* d_in, const int* in_sizes, int n_in,
                              void* d_out, int out_size) {
    const float* x    = (const float*)d_in[0];   // [64,512]
    const float* W    = (const float*)d_in[1];   // [512,2048]
    const float* bias = (const float*)d_in[2];   // [2048]
    const float* a    = (const float*)d_in[3];   // [512]
    const float* Oxy  = (const float*)d_in[4];   // [512]
    float* out = (float*)d_out;                  // [64]

    z_part_kernel<<<dim3(HDIM / 256, BDIM / 16, NSPLIT), 256>>>(W, x);
    z_comb_kernel<<<256, 256>>>(bias);
    prod_kernel<<<dim3(KP / 32, 1, NCHUNK), 256>>>(W, x);
    reduce_kernel<<<BDIM, 1024>>>(x, a, Oxy, out);
}